// round 1
// baseline (speedup 1.0000x reference)
#include <cuda_runtime.h>
#include <cstdint>
#include <cstddef>

// Problem constants (fixed by setup_inputs)
#define NC 300000      // n_clauses
#define NL 200000      // n_lits
#define HALFL 100000   // n_lits / 2
#define LDIM 128
#define CDIM 128

// ---------------- static scratch (no allocation allowed) ----------------
__device__ float g_Lh  [(size_t)NL * 128];   // literal embeddings
__device__ float g_Lmsg[(size_t)NL * 128];   // L message / reused as Lnew
__device__ float g_Lhid[(size_t)NL * 128];   // L MLP hidden
__device__ float g_Cmsg[(size_t)NC * 256];   // clause message / reused as V
__device__ float g_Chid[(size_t)NC * 256];   // clause MLP hidden / reused as Vhid
__device__ float g_C   [(size_t)NC * 128];   // clause embeddings (normalized)
__device__ float g_Shid[(size_t)NC * 128];   // Cs hidden
__device__ float g_stats[512];               // [0:128) colsum [128:256) colsumsq
                                             // [256:384) mean  [384:512) rstd

// ---------------- helpers ----------------
__device__ __forceinline__ void red_add_v4(float* addr, float4 v) {
    asm volatile("red.global.add.v4.f32 [%0], {%1,%2,%3,%4};"
                 :: "l"(addr), "f"(v.x), "f"(v.y), "f"(v.z), "f"(v.w)
                 : "memory");
}

__device__ __forceinline__ float warp_sum(float v) {
    #pragma unroll
    for (int o = 16; o > 0; o >>= 1) v += __shfl_xor_sync(0xFFFFFFFFu, v, o);
    return v;
}

// ---------------- init: broadcast L_init to all literal rows ----------------
__global__ void init_Lh(const float* __restrict__ L_init) {
    int idx = blockIdx.x * blockDim.x + threadIdx.x;   // one float4 each
    int total = NL * 32;
    if (idx >= total) return;
    int c4 = (idx & 31) * 4;
    float4 v = *(const float4*)&L_init[c4];
    *(float4*)&g_Lh[(size_t)idx * 4] = v;
}

// ---------------- edge scatter: clause side ----------------
// C_msg[cl] += [Lh[lit], Lh[flip(lit)]]   (one warp per edge)
__global__ void scatter_clause(const int* __restrict__ lit_idx,
                               const int* __restrict__ cl_idx, int n_edges) {
    int e    = (blockIdx.x * blockDim.x + threadIdx.x) >> 5;
    int lane = threadIdx.x & 31;
    if (e >= n_edges) return;
    int lit  = lit_idx[e];
    int cl   = cl_idx[e];
    int flip = (lit >= HALFL) ? (lit - HALFL) : (lit + HALFL);
    float4 a = *(const float4*)&g_Lh[(size_t)lit  * 128 + lane * 4];
    float4 b = *(const float4*)&g_Lh[(size_t)flip * 128 + lane * 4];
    float* p = &g_Cmsg[(size_t)cl * 256 + lane * 4];
    red_add_v4(p,       a);
    red_add_v4(p + 128, b);
}

// ---------------- edge scatter: literal side ----------------
// L_msg[lit] += C[cl]   (one warp per edge)
__global__ void scatter_lit(const int* __restrict__ lit_idx,
                            const int* __restrict__ cl_idx, int n_edges) {
    int e    = (blockIdx.x * blockDim.x + threadIdx.x) >> 5;
    int lane = threadIdx.x & 31;
    if (e >= n_edges) return;
    int lit = lit_idx[e];
    int cl  = cl_idx[e];
    float4 c = *(const float4*)&g_C[(size_t)cl * 128 + lane * 4];
    red_add_v4(&g_Lmsg[(size_t)lit * 128 + lane * 4], c);
}

// ---------------- SGEMM: Out[M,N] = (relu?)(A[M,K] @ W[K,N] + bias) ----------------
// BM=128, BN=128, BK=16, 256 threads, 8x8 per-thread tile. Requires N % 128 == 0, K % 16 == 0.
template<bool RELU>
__global__ __launch_bounds__(256)
void sgemm(const float* __restrict__ A, const float* __restrict__ W,
           const float* __restrict__ bias, float* __restrict__ Out,
           int M, int K, int N) {
    __shared__ float As[16][128];
    __shared__ float Bs[16][128];

    int tid  = threadIdx.x;
    int brow = blockIdx.y * 128;
    int bcol = blockIdx.x * 128;
    int trow = (tid / 16) * 8;
    int tcol = (tid % 16) * 8;

    float acc[8][8];
    #pragma unroll
    for (int i = 0; i < 8; i++)
        #pragma unroll
        for (int j = 0; j < 8; j++) acc[i][j] = 0.f;

    for (int k0 = 0; k0 < K; k0 += 16) {
        // load A tile (128x16) -> As transposed [k][m]
        #pragma unroll
        for (int t = 0; t < 2; t++) {
            int f4 = tid + t * 256;          // 0..511
            int r  = f4 >> 2;                // 0..127
            int c4 = (f4 & 3) * 4;           // 0,4,8,12
            int gr = brow + r;
            float4 v = make_float4(0.f, 0.f, 0.f, 0.f);
            if (gr < M) v = *(const float4*)&A[(size_t)gr * K + k0 + c4];
            As[c4 + 0][r] = v.x; As[c4 + 1][r] = v.y;
            As[c4 + 2][r] = v.z; As[c4 + 3][r] = v.w;
        }
        // load W tile (16x128) -> Bs [k][n]
        #pragma unroll
        for (int t = 0; t < 2; t++) {
            int f4 = tid + t * 256;          // 0..511
            int r  = f4 >> 5;                // 0..15
            int c4 = (f4 & 31) * 4;          // 0..124
            float4 v = *(const float4*)&W[(size_t)(k0 + r) * N + bcol + c4];
            *(float4*)&Bs[r][c4] = v;
        }
        __syncthreads();

        #pragma unroll
        for (int kk = 0; kk < 16; kk++) {
            float a[8], b[8];
            *(float4*)&a[0] = *(const float4*)&As[kk][trow];
            *(float4*)&a[4] = *(const float4*)&As[kk][trow + 4];
            *(float4*)&b[0] = *(const float4*)&Bs[kk][tcol];
            *(float4*)&b[4] = *(const float4*)&Bs[kk][tcol + 4];
            #pragma unroll
            for (int i = 0; i < 8; i++)
                #pragma unroll
                for (int j = 0; j < 8; j++)
                    acc[i][j] = fmaf(a[i], b[j], acc[i][j]);
        }
        __syncthreads();
    }

    // epilogue: bias (+relu), vectorized stores
    #pragma unroll
    for (int i = 0; i < 8; i++) {
        int gr = brow + trow + i;
        if (gr >= M) continue;
        float4 o0, o1;
        float* pacc = acc[i];
        o0.x = pacc[0] + bias[bcol + tcol + 0];
        o0.y = pacc[1] + bias[bcol + tcol + 1];
        o0.z = pacc[2] + bias[bcol + tcol + 2];
        o0.w = pacc[3] + bias[bcol + tcol + 3];
        o1.x = pacc[4] + bias[bcol + tcol + 4];
        o1.y = pacc[5] + bias[bcol + tcol + 5];
        o1.z = pacc[6] + bias[bcol + tcol + 6];
        o1.w = pacc[7] + bias[bcol + tcol + 7];
        if (RELU) {
            o0.x = fmaxf(o0.x, 0.f); o0.y = fmaxf(o0.y, 0.f);
            o0.z = fmaxf(o0.z, 0.f); o0.w = fmaxf(o0.w, 0.f);
            o1.x = fmaxf(o1.x, 0.f); o1.y = fmaxf(o1.y, 0.f);
            o1.z = fmaxf(o1.z, 0.f); o1.w = fmaxf(o1.w, 0.f);
        }
        *(float4*)&Out[(size_t)gr * N + bcol + tcol]     = o0;
        *(float4*)&Out[(size_t)gr * N + bcol + tcol + 4] = o1;
    }
}

// ---------------- column stats over C [M,128]: sum & sumsq partials ----------------
__global__ void col_stats(int M) {
    int col = threadIdx.x;   // 128 threads
    float s = 0.f, ss = 0.f;
    for (int r = blockIdx.x; r < M; r += gridDim.x) {
        float v = g_C[(size_t)r * 128 + col];
        s  += v;
        ss += v * v;
    }
    atomicAdd(&g_stats[col],       s);
    atomicAdd(&g_stats[128 + col], ss);
}

__global__ void finalize_stats(int M) {
    int col = threadIdx.x;   // 128 threads
    float n    = (float)M;
    float sum  = g_stats[col];
    float sumq = g_stats[128 + col];
    float mean = sum / n;
    float var  = (sumq - n * mean * mean) / (n - 1.0f);   // ddof=1
    var = fmaxf(var, 0.f);
    float rstd = 1.0f / (sqrtf(var) + 1e-10f);
    g_stats[256 + col] = mean;
    g_stats[384 + col] = rstd;
}

__global__ void normalize_C() {
    int idx = blockIdx.x * blockDim.x + threadIdx.x;   // one float4 each
    int total = NC * 32;
    if (idx >= total) return;
    int c4 = (idx & 31) * 4;
    float4 v = *(const float4*)&g_C[(size_t)idx * 4];
    float4 m = *(const float4*)&g_stats[256 + c4];
    float4 r = *(const float4*)&g_stats[384 + c4];
    v.x = (v.x - m.x) * r.x; v.y = (v.y - m.y) * r.y;
    v.z = (v.z - m.z) * r.z; v.w = (v.w - m.w) * r.w;
    *(float4*)&g_C[(size_t)idx * 4] = v;
}

// ---------------- Lh = LayerNorm(Lnew + 0.1*Lh) * g + b  (one warp per row) ----------------
__global__ void add_ln(const float* __restrict__ Lnew,
                       const float* __restrict__ lng,
                       const float* __restrict__ lnb, int M) {
    int row  = (blockIdx.x * blockDim.x + threadIdx.x) >> 5;
    int lane = threadIdx.x & 31;
    if (row >= M) return;
    size_t base = (size_t)row * 128 + lane * 4;
    float4 xn = *(const float4*)&Lnew[base];
    float4 xo = *(const float4*)&g_Lh[base];
    float4 x;
    x.x = fmaf(0.1f, xo.x, xn.x); x.y = fmaf(0.1f, xo.y, xn.y);
    x.z = fmaf(0.1f, xo.z, xn.z); x.w = fmaf(0.1f, xo.w, xn.w);
    float mean = warp_sum(x.x + x.y + x.z + x.w) * (1.0f / 128.0f);
    float dx = x.x - mean, dy = x.y - mean, dz = x.z - mean, dw = x.w - mean;
    float var = warp_sum(dx * dx + dy * dy + dz * dz + dw * dw) * (1.0f / 128.0f);
    float rstd = rsqrtf(var + 1e-5f);
    float4 gg = *(const float4*)&lng[lane * 4];
    float4 bb = *(const float4*)&lnb[lane * 4];
    float4 y;
    y.x = fmaf(dx * rstd, gg.x, bb.x);
    y.y = fmaf(dy * rstd, gg.y, bb.y);
    y.z = fmaf(dz * rstd, gg.z, bb.z);
    y.w = fmaf(dw * rstd, gg.w, bb.w);
    *(float4*)&g_Lh[base] = y;
}

// ---------------- V = [Lh[:half], Lh[half:]] written into g_Cmsg ----------------
__global__ void concat_V() {
    int idx = blockIdx.x * blockDim.x + threadIdx.x;   // one float4 each
    int total = HALFL * 64;
    if (idx >= total) return;
    int v  = idx >> 6;
    int c4 = idx & 63;
    float4 x;
    if (c4 < 32) x = *(const float4*)&g_Lh[(size_t)v * 128 + c4 * 4];
    else         x = *(const float4*)&g_Lh[(size_t)(v + HALFL) * 128 + (c4 - 32) * 4];
    *(float4*)&g_Cmsg[(size_t)v * 256 + c4 * 4] = x;
}

// ---------------- out[m] = dot(H[m,:K], w) + b   (one warp per row) ----------------
template<int K>
__global__ void rowdot(const float* __restrict__ H, const float* __restrict__ w,
                       const float* __restrict__ b, float* __restrict__ out, int M) {
    int row  = (blockIdx.x * blockDim.x + threadIdx.x) >> 5;
    int lane = threadIdx.x & 31;
    if (row >= M) return;
    float acc = 0.f;
    #pragma unroll
    for (int k0 = 0; k0 < K; k0 += 128) {
        float4 h  = *(const float4*)&H[(size_t)row * K + k0 + lane * 4];
        float4 ww = *(const float4*)&w[k0 + lane * 4];
        acc = fmaf(h.x, ww.x, acc);
        acc = fmaf(h.y, ww.y, acc);
        acc = fmaf(h.z, ww.z, acc);
        acc = fmaf(h.w, ww.w, acc);
    }
    acc = warp_sum(acc);
    if (lane == 0) out[row] = acc + b[0];
}

// ---------------- host orchestration ----------------
extern "C" void kernel_launch(void* const* d_in, const int* in_sizes, int n_in,
                              void* d_out, int out_size) {
    const float* L_init = (const float*)d_in[0];
    const float* ln_g   = (const float*)d_in[1];
    const float* ln_b   = (const float*)d_in[2];
    const float* Cu_W1  = (const float*)d_in[3];
    const float* Cu_b1  = (const float*)d_in[4];
    const float* Cu_W2  = (const float*)d_in[5];
    const float* Cu_b2  = (const float*)d_in[6];
    const float* Lu_W1  = (const float*)d_in[7];
    const float* Lu_b1  = (const float*)d_in[8];
    const float* Lu_W2  = (const float*)d_in[9];
    const float* Lu_b2  = (const float*)d_in[10];
    const float* Vd_W1  = (const float*)d_in[11];
    const float* Vd_b1  = (const float*)d_in[12];
    const float* Vd_W2  = (const float*)d_in[13];
    const float* Vd_b2  = (const float*)d_in[14];
    const float* Vc_W1  = (const float*)d_in[15];
    const float* Vc_b1  = (const float*)d_in[16];
    const float* Vc_W2  = (const float*)d_in[17];
    const float* Vc_b2  = (const float*)d_in[18];
    const float* Cs_W1  = (const float*)d_in[19];
    const float* Cs_b1  = (const float*)d_in[20];
    const float* Cs_W2  = (const float*)d_in[21];
    const float* Cs_b2  = (const float*)d_in[22];
    const int* clause_idx = (const int*)d_in[23];
    const int* lit_idx    = (const int*)d_in[24];
    int n_edges = in_sizes[23];
    float* out = (float*)d_out;

    void *pCmsg, *pLmsg, *pChid, *pC, *pShid, *pStats;
    cudaGetSymbolAddress(&pCmsg,  g_Cmsg);
    cudaGetSymbolAddress(&pLmsg,  g_Lmsg);
    cudaGetSymbolAddress(&pChid,  g_Chid);
    cudaGetSymbolAddress(&pC,     g_C);
    cudaGetSymbolAddress(&pShid,  g_Shid);
    cudaGetSymbolAddress(&pStats, g_stats);
    float* Cmsg = (float*)pCmsg;
    float* Lmsg = (float*)pLmsg;
    float* Chid = (float*)pChid;
    float* C    = (float*)pC;
    float* Shid = (float*)pShid;

    const int eblocks = (n_edges + 7) / 8;   // one warp per edge, 8 warps/block

    init_Lh<<<(NL * 32 + 255) / 256, 256>>>(L_init);

    for (int hop = 0; hop < 4; hop++) {
        // ---- clause update ----
        cudaMemsetAsync(Cmsg, 0, (size_t)NC * 256 * sizeof(float));
        scatter_clause<<<eblocks, 256>>>(lit_idx, clause_idx, n_edges);
        sgemm<true ><<<dim3(2, (NC + 127) / 128), 256>>>(Cmsg, Cu_W1, Cu_b1, Chid, NC, 256, 256);
        sgemm<false><<<dim3(1, (NC + 127) / 128), 256>>>(Chid, Cu_W2, Cu_b2, C,    NC, 256, 128);
        cudaMemsetAsync(pStats, 0, 512 * sizeof(float));
        col_stats<<<1024, 128>>>(NC);
        finalize_stats<<<1, 128>>>(NC);
        normalize_C<<<(NC * 32 + 255) / 256, 256>>>();
        // ---- literal update ----
        cudaMemsetAsync(Lmsg, 0, (size_t)NL * 128 * sizeof(float));
        scatter_lit<<<eblocks, 256>>>(lit_idx, clause_idx, n_edges);
        sgemm<true ><<<dim3(1, (NL + 127) / 128), 256>>>(Lmsg, Lu_W1, Lu_b1, g_Lhid, NL, 128, 128);
        sgemm<false><<<dim3(1, (NL + 127) / 128), 256>>>(g_Lhid, Lu_W2, Lu_b2, Lmsg, NL, 128, 128);
        add_ln<<<(NL + 7) / 8, 256>>>(Lmsg, ln_g, ln_b, NL);
    }

    // ---- heads ----
    concat_V<<<(HALFL * 64 + 255) / 256, 256>>>();   // V lives in g_Cmsg
    sgemm<true><<<dim3(2, (HALFL + 127) / 128), 256>>>(Cmsg, Vd_W1, Vd_b1, Chid, HALFL, 256, 256);
    rowdot<256><<<(HALFL + 7) / 8, 256>>>(Chid, Vd_W2, Vd_b2, out, HALFL);
    sgemm<true><<<dim3(2, (HALFL + 127) / 128), 256>>>(Cmsg, Vc_W1, Vc_b1, Chid, HALFL, 256, 256);
    rowdot<256><<<(HALFL + 7) / 8, 256>>>(Chid, Vc_W2, Vc_b2, out + HALFL, HALFL);
    sgemm<true><<<dim3(1, (NC + 127) / 128), 256>>>(C, Cs_W1, Cs_b1, Shid, NC, 128, 128);
    rowdot<128><<<(NC + 7) / 8, 256>>>(Shid, Cs_W2, Cs_b2, out + 2 * HALFL, NC);
}

// round 2
// speedup vs baseline: 1.6655x; 1.6655x over previous
#include <cuda_runtime.h>
#include <cstdint>
#include <cstddef>

// Problem constants (fixed by setup_inputs)
#define NC 300000      // n_clauses
#define NL 200000      // n_lits
#define HALFL 100000   // n_lits / 2
#define NE_MAX 1000000 // n_edges

// ---------------- static scratch (no allocation allowed) ----------------
__device__ float g_Lh  [(size_t)NL * 128];   // literal embeddings
__device__ float g_Lmsg[(size_t)NL * 128];   // L message / reused as Lnew
__device__ float g_Lhid[(size_t)NL * 128];   // L MLP hidden
__device__ float g_Cmsg[(size_t)NC * 256];   // clause message / reused as V
__device__ float g_Chid[(size_t)NC * 256];   // clause MLP hidden / reused as Vhid
__device__ float g_C   [(size_t)NC * 128];   // clause embeddings (normalized)
__device__ float g_Shid[(size_t)NC * 128];   // Cs hidden
__device__ float g_stats[512];               // colsum | colsumsq | mean | rstd

// CSR scratch
__device__ int g_deg_c[NC];
__device__ int g_off_c[NC];
__device__ int g_cur_c[NC];
__device__ int g_csr_c[NE_MAX];   // lit ids grouped by clause
__device__ int g_deg_l[NL];
__device__ int g_off_l[NL];
__device__ int g_cur_l[NL];
__device__ int g_csr_l[NE_MAX];   // clause ids grouped by lit
__device__ int g_bsums[1024];     // scan block sums

// ---------------- helpers ----------------
__device__ __forceinline__ float warp_sum(float v) {
    #pragma unroll
    for (int o = 16; o > 0; o >>= 1) v += __shfl_xor_sync(0xFFFFFFFFu, v, o);
    return v;
}
__device__ __forceinline__ int warp_sum_i(int v) {
    #pragma unroll
    for (int o = 16; o > 0; o >>= 1) v += __shfl_xor_sync(0xFFFFFFFFu, v, o);
    return v;
}

// ---------------- CSR build ----------------
__global__ void histogram(const int* __restrict__ key, int* __restrict__ deg, int ne) {
    int e = blockIdx.x * blockDim.x + threadIdx.x;
    if (e < ne) atomicAdd(&deg[key[e]], 1);
}

// per-1024-chunk sums
__global__ void block_sums(const int* __restrict__ deg, int* __restrict__ bsums, int n) {
    __shared__ int total;
    int b = blockIdx.x, t = threadIdx.x;
    if (t == 0) total = 0;
    __syncthreads();
    int base = b * 1024;
    int s = 0;
    for (int i = t; i < 1024; i += 256) {
        int idx = base + i;
        if (idx < n) s += deg[idx];
    }
    s = warp_sum_i(s);
    if ((t & 31) == 0) atomicAdd(&total, s);
    __syncthreads();
    if (t == 0) bsums[b] = total;
}

// single-block exclusive scan of bsums (G <= 512)
__global__ void scan_bsums(int* bsums, int G) {
    __shared__ int sh[512];
    int t = threadIdx.x;
    int v = (t < G) ? bsums[t] : 0;
    sh[t] = v;
    __syncthreads();
    #pragma unroll
    for (int o = 1; o < 512; o <<= 1) {
        int u = (t >= o) ? sh[t - o] : 0;
        __syncthreads();
        sh[t] += u;
        __syncthreads();
    }
    if (t < G) bsums[t] = sh[t] - v;   // exclusive
}

// per-chunk exclusive scan + add block prefix -> off
__global__ void scan_chunks(const int* __restrict__ deg, const int* __restrict__ bsums,
                            int* __restrict__ off, int n) {
    __shared__ int th[256];
    int b = blockIdx.x, t = threadIdx.x;
    int base = b * 1024 + t * 4;
    int v0 = 0, v1 = 0, v2 = 0, v3 = 0;
    if (base + 0 < n) v0 = deg[base + 0];
    if (base + 1 < n) v1 = deg[base + 1];
    if (base + 2 < n) v2 = deg[base + 2];
    if (base + 3 < n) v3 = deg[base + 3];
    int s = v0 + v1 + v2 + v3;
    th[t] = s;
    __syncthreads();
    #pragma unroll
    for (int o = 1; o < 256; o <<= 1) {
        int u = (t >= o) ? th[t - o] : 0;
        __syncthreads();
        th[t] += u;
        __syncthreads();
    }
    int pre = bsums[b] + th[t] - s;   // exclusive prefix for this thread
    if (base + 0 < n) off[base + 0] = pre;
    pre += v0;
    if (base + 1 < n) off[base + 1] = pre;
    pre += v1;
    if (base + 2 < n) off[base + 2] = pre;
    pre += v2;
    if (base + 3 < n) off[base + 3] = pre;
}

__global__ void fill_csr(const int* __restrict__ key, const int* __restrict__ val,
                         const int* __restrict__ off, int* __restrict__ cur,
                         int* __restrict__ out, int ne) {
    int e = blockIdx.x * blockDim.x + threadIdx.x;
    if (e >= ne) return;
    int k = key[e];
    int p = off[k] + atomicAdd(&cur[k], 1);
    out[p] = val[e];
}

// ---------------- init: broadcast L_init to all literal rows ----------------
__global__ void init_Lh(const float* __restrict__ L_init) {
    int idx = blockIdx.x * blockDim.x + threadIdx.x;   // one float4 each
    int total = NL * 32;
    if (idx >= total) return;
    int c4 = (idx & 31) * 4;
    float4 v = *(const float4*)&L_init[c4];
    *(float4*)&g_Lh[(size_t)idx * 4] = v;
}

// ---------------- gather: clause side (one warp per clause, no atomics) ----------------
__global__ void gather_clause() {
    int c    = (blockIdx.x * blockDim.x + threadIdx.x) >> 5;
    int lane = threadIdx.x & 31;
    if (c >= NC) return;
    int o = g_off_c[c];
    int d = g_deg_c[c];
    float4 a = make_float4(0.f, 0.f, 0.f, 0.f);
    float4 b = make_float4(0.f, 0.f, 0.f, 0.f);
    for (int i = 0; i < d; i++) {
        int lit  = g_csr_c[o + i];
        int flip = (lit >= HALFL) ? (lit - HALFL) : (lit + HALFL);
        float4 x = *(const float4*)&g_Lh[(size_t)lit  * 128 + lane * 4];
        float4 y = *(const float4*)&g_Lh[(size_t)flip * 128 + lane * 4];
        a.x += x.x; a.y += x.y; a.z += x.z; a.w += x.w;
        b.x += y.x; b.y += y.y; b.z += y.z; b.w += y.w;
    }
    float* p = &g_Cmsg[(size_t)c * 256 + lane * 4];
    *(float4*)p         = a;
    *(float4*)(p + 128) = b;
}

// ---------------- gather: literal side ----------------
__global__ void gather_lit() {
    int l    = (blockIdx.x * blockDim.x + threadIdx.x) >> 5;
    int lane = threadIdx.x & 31;
    if (l >= NL) return;
    int o = g_off_l[l];
    int d = g_deg_l[l];
    float4 a = make_float4(0.f, 0.f, 0.f, 0.f);
    for (int i = 0; i < d; i++) {
        int cl = g_csr_l[o + i];
        float4 x = *(const float4*)&g_C[(size_t)cl * 128 + lane * 4];
        a.x += x.x; a.y += x.y; a.z += x.z; a.w += x.w;
    }
    *(float4*)&g_Lmsg[(size_t)l * 128 + lane * 4] = a;
}

// ---------------- SGEMM: Out[M,N] = (relu?)(A[M,K] @ W[K,N] + bias) ----------------
// BM=128, BN=128, BK=16, 256 threads, 8x8 per-thread tile. K,N compile-time.
template<bool RELU, int K, int N>
__global__ __launch_bounds__(256)
void sgemm(const float* __restrict__ A, const float* __restrict__ W,
           const float* __restrict__ bias, float* __restrict__ Out, int M) {
    __shared__ float As[16][128];
    __shared__ float Bs[16][128];

    int tid  = threadIdx.x;
    int brow = blockIdx.y * 128;
    int bcol = blockIdx.x * 128;
    int trow = (tid / 16) * 8;
    int tcol = (tid % 16) * 8;

    float acc[8][8];
    #pragma unroll
    for (int i = 0; i < 8; i++)
        #pragma unroll
        for (int j = 0; j < 8; j++) acc[i][j] = 0.f;

    #pragma unroll 1
    for (int k0 = 0; k0 < K; k0 += 16) {
        #pragma unroll
        for (int t = 0; t < 2; t++) {
            int f4 = tid + t * 256;          // 0..511
            int r  = f4 >> 2;                // 0..127
            int c4 = (f4 & 3) * 4;           // 0,4,8,12
            int gr = brow + r;
            float4 v = make_float4(0.f, 0.f, 0.f, 0.f);
            if (gr < M) v = *(const float4*)&A[(size_t)gr * K + k0 + c4];
            As[c4 + 0][r] = v.x; As[c4 + 1][r] = v.y;
            As[c4 + 2][r] = v.z; As[c4 + 3][r] = v.w;
        }
        #pragma unroll
        for (int t = 0; t < 2; t++) {
            int f4 = tid + t * 256;          // 0..511
            int r  = f4 >> 5;                // 0..15
            int c4 = (f4 & 31) * 4;          // 0..124
            float4 v = *(const float4*)&W[(size_t)(k0 + r) * N + bcol + c4];
            *(float4*)&Bs[r][c4] = v;
        }
        __syncthreads();

        #pragma unroll
        for (int kk = 0; kk < 16; kk++) {
            float a[8], b[8];
            *(float4*)&a[0] = *(const float4*)&As[kk][trow];
            *(float4*)&a[4] = *(const float4*)&As[kk][trow + 4];
            *(float4*)&b[0] = *(const float4*)&Bs[kk][tcol];
            *(float4*)&b[4] = *(const float4*)&Bs[kk][tcol + 4];
            #pragma unroll
            for (int i = 0; i < 8; i++)
                #pragma unroll
                for (int j = 0; j < 8; j++)
                    acc[i][j] = fmaf(a[i], b[j], acc[i][j]);
        }
        __syncthreads();
    }

    #pragma unroll
    for (int i = 0; i < 8; i++) {
        int gr = brow + trow + i;
        if (gr >= M) continue;
        float4 o0, o1;
        float* pacc = acc[i];
        o0.x = pacc[0] + bias[bcol + tcol + 0];
        o0.y = pacc[1] + bias[bcol + tcol + 1];
        o0.z = pacc[2] + bias[bcol + tcol + 2];
        o0.w = pacc[3] + bias[bcol + tcol + 3];
        o1.x = pacc[4] + bias[bcol + tcol + 4];
        o1.y = pacc[5] + bias[bcol + tcol + 5];
        o1.z = pacc[6] + bias[bcol + tcol + 6];
        o1.w = pacc[7] + bias[bcol + tcol + 7];
        if (RELU) {
            o0.x = fmaxf(o0.x, 0.f); o0.y = fmaxf(o0.y, 0.f);
            o0.z = fmaxf(o0.z, 0.f); o0.w = fmaxf(o0.w, 0.f);
            o1.x = fmaxf(o1.x, 0.f); o1.y = fmaxf(o1.y, 0.f);
            o1.z = fmaxf(o1.z, 0.f); o1.w = fmaxf(o1.w, 0.f);
        }
        *(float4*)&Out[(size_t)gr * N + bcol + tcol]     = o0;
        *(float4*)&Out[(size_t)gr * N + bcol + tcol + 4] = o1;
    }
}

// ---------------- column stats over C [M,128] ----------------
__global__ void col_stats(int M) {
    int col = threadIdx.x;   // 128 threads
    float s = 0.f, ss = 0.f;
    for (int r = blockIdx.x; r < M; r += gridDim.x) {
        float v = g_C[(size_t)r * 128 + col];
        s  += v;
        ss += v * v;
    }
    atomicAdd(&g_stats[col],       s);
    atomicAdd(&g_stats[128 + col], ss);
}

__global__ void finalize_stats(int M) {
    int col = threadIdx.x;   // 128 threads
    float n    = (float)M;
    float sum  = g_stats[col];
    float sumq = g_stats[128 + col];
    float mean = sum / n;
    float var  = (sumq - n * mean * mean) / (n - 1.0f);   // ddof=1
    var = fmaxf(var, 0.f);
    float rstd = 1.0f / (sqrtf(var) + 1e-10f);
    g_stats[256 + col] = mean;
    g_stats[384 + col] = rstd;
}

__global__ void normalize_C() {
    int idx = blockIdx.x * blockDim.x + threadIdx.x;   // one float4 each
    int total = NC * 32;
    if (idx >= total) return;
    int c4 = (idx & 31) * 4;
    float4 v = *(const float4*)&g_C[(size_t)idx * 4];
    float4 m = *(const float4*)&g_stats[256 + c4];
    float4 r = *(const float4*)&g_stats[384 + c4];
    v.x = (v.x - m.x) * r.x; v.y = (v.y - m.y) * r.y;
    v.z = (v.z - m.z) * r.z; v.w = (v.w - m.w) * r.w;
    *(float4*)&g_C[(size_t)idx * 4] = v;
}

// ---------------- Lh = LayerNorm(Lnew + 0.1*Lh) * g + b ----------------
__global__ void add_ln(const float* __restrict__ Lnew,
                       const float* __restrict__ lng,
                       const float* __restrict__ lnb, int M) {
    int row  = (blockIdx.x * blockDim.x + threadIdx.x) >> 5;
    int lane = threadIdx.x & 31;
    if (row >= M) return;
    size_t base = (size_t)row * 128 + lane * 4;
    float4 xn = *(const float4*)&Lnew[base];
    float4 xo = *(const float4*)&g_Lh[base];
    float4 x;
    x.x = fmaf(0.1f, xo.x, xn.x); x.y = fmaf(0.1f, xo.y, xn.y);
    x.z = fmaf(0.1f, xo.z, xn.z); x.w = fmaf(0.1f, xo.w, xn.w);
    float mean = warp_sum(x.x + x.y + x.z + x.w) * (1.0f / 128.0f);
    float dx = x.x - mean, dy = x.y - mean, dz = x.z - mean, dw = x.w - mean;
    float var = warp_sum(dx * dx + dy * dy + dz * dz + dw * dw) * (1.0f / 128.0f);
    float rstd = rsqrtf(var + 1e-5f);
    float4 gg = *(const float4*)&lng[lane * 4];
    float4 bb = *(const float4*)&lnb[lane * 4];
    float4 y;
    y.x = fmaf(dx * rstd, gg.x, bb.x);
    y.y = fmaf(dy * rstd, gg.y, bb.y);
    y.z = fmaf(dz * rstd, gg.z, bb.z);
    y.w = fmaf(dw * rstd, gg.w, bb.w);
    *(float4*)&g_Lh[base] = y;
}

// ---------------- V = [Lh[:half], Lh[half:]] written into g_Cmsg ----------------
__global__ void concat_V() {
    int idx = blockIdx.x * blockDim.x + threadIdx.x;   // one float4 each
    int total = HALFL * 64;
    if (idx >= total) return;
    int v  = idx >> 6;
    int c4 = idx & 63;
    float4 x;
    if (c4 < 32) x = *(const float4*)&g_Lh[(size_t)v * 128 + c4 * 4];
    else         x = *(const float4*)&g_Lh[(size_t)(v + HALFL) * 128 + (c4 - 32) * 4];
    *(float4*)&g_Cmsg[(size_t)v * 256 + c4 * 4] = x;
}

// ---------------- out[m] = dot(H[m,:K], w) + b ----------------
template<int K>
__global__ void rowdot(const float* __restrict__ H, const float* __restrict__ w,
                       const float* __restrict__ b, float* __restrict__ out, int M) {
    int row  = (blockIdx.x * blockDim.x + threadIdx.x) >> 5;
    int lane = threadIdx.x & 31;
    if (row >= M) return;
    float acc = 0.f;
    #pragma unroll
    for (int k0 = 0; k0 < K; k0 += 128) {
        float4 h  = *(const float4*)&H[(size_t)row * K + k0 + lane * 4];
        float4 ww = *(const float4*)&w[k0 + lane * 4];
        acc = fmaf(h.x, ww.x, acc);
        acc = fmaf(h.y, ww.y, acc);
        acc = fmaf(h.z, ww.z, acc);
        acc = fmaf(h.w, ww.w, acc);
    }
    acc = warp_sum(acc);
    if (lane == 0) out[row] = acc + b[0];
}

// ---------------- host orchestration ----------------
extern "C" void kernel_launch(void* const* d_in, const int* in_sizes, int n_in,
                              void* d_out, int out_size) {
    const float* L_init = (const float*)d_in[0];
    const float* ln_g   = (const float*)d_in[1];
    const float* ln_b   = (const float*)d_in[2];
    const float* Cu_W1  = (const float*)d_in[3];
    const float* Cu_b1  = (const float*)d_in[4];
    const float* Cu_W2  = (const float*)d_in[5];
    const float* Cu_b2  = (const float*)d_in[6];
    const float* Lu_W1  = (const float*)d_in[7];
    const float* Lu_b1  = (const float*)d_in[8];
    const float* Lu_W2  = (const float*)d_in[9];
    const float* Lu_b2  = (const float*)d_in[10];
    const float* Vd_W1  = (const float*)d_in[11];
    const float* Vd_b1  = (const float*)d_in[12];
    const float* Vd_W2  = (const float*)d_in[13];
    const float* Vd_b2  = (const float*)d_in[14];
    const float* Vc_W1  = (const float*)d_in[15];
    const float* Vc_b1  = (const float*)d_in[16];
    const float* Vc_W2  = (const float*)d_in[17];
    const float* Vc_b2  = (const float*)d_in[18];
    const float* Cs_W1  = (const float*)d_in[19];
    const float* Cs_b1  = (const float*)d_in[20];
    const float* Cs_W2  = (const float*)d_in[21];
    const float* Cs_b2  = (const float*)d_in[22];
    const int* clause_idx = (const int*)d_in[23];
    const int* lit_idx    = (const int*)d_in[24];
    int n_edges = in_sizes[23];
    float* out = (float*)d_out;

    void *pCmsg, *pChid, *pC, *pShid, *pStats;
    void *pDegC, *pCurC, *pDegL, *pCurL, *pOffC, *pOffL, *pCsrC, *pCsrL, *pBsums;
    cudaGetSymbolAddress(&pCmsg,  g_Cmsg);
    cudaGetSymbolAddress(&pChid,  g_Chid);
    cudaGetSymbolAddress(&pC,     g_C);
    cudaGetSymbolAddress(&pShid,  g_Shid);
    cudaGetSymbolAddress(&pStats, g_stats);
    cudaGetSymbolAddress(&pDegC,  g_deg_c);
    cudaGetSymbolAddress(&pCurC,  g_cur_c);
    cudaGetSymbolAddress(&pDegL,  g_deg_l);
    cudaGetSymbolAddress(&pCurL,  g_cur_l);
    cudaGetSymbolAddress(&pOffC,  g_off_c);
    cudaGetSymbolAddress(&pOffL,  g_off_l);
    cudaGetSymbolAddress(&pCsrC,  g_csr_c);
    cudaGetSymbolAddress(&pCsrL,  g_csr_l);
    cudaGetSymbolAddress(&pBsums, g_bsums);
    float* Cmsg = (float*)pCmsg;
    float* Chid = (float*)pChid;
    float* C    = (float*)pC;
    float* Shid = (float*)pShid;
    void  *pLmsg, *pLhid;
    cudaGetSymbolAddress(&pLmsg, g_Lmsg);
    cudaGetSymbolAddress(&pLhid, g_Lhid);
    float* Lmsg = (float*)pLmsg;
    float* Lhid = (float*)pLhid;

    const int EB = (n_edges + 255) / 256;

    // ---- build CSR (clause side) ----
    cudaMemsetAsync(pDegC, 0, NC * sizeof(int));
    cudaMemsetAsync(pCurC, 0, NC * sizeof(int));
    histogram<<<EB, 256>>>(clause_idx, (int*)pDegC, n_edges);
    {
        int G = (NC + 1023) / 1024;
        block_sums<<<G, 256>>>((int*)pDegC, (int*)pBsums, NC);
        scan_bsums<<<1, 512>>>((int*)pBsums, G);
        scan_chunks<<<G, 256>>>((int*)pDegC, (int*)pBsums, (int*)pOffC, NC);
    }
    fill_csr<<<EB, 256>>>(clause_idx, lit_idx, (int*)pOffC, (int*)pCurC, (int*)pCsrC, n_edges);

    // ---- build CSR (literal side) ----
    cudaMemsetAsync(pDegL, 0, NL * sizeof(int));
    cudaMemsetAsync(pCurL, 0, NL * sizeof(int));
    histogram<<<EB, 256>>>(lit_idx, (int*)pDegL, n_edges);
    {
        int G = (NL + 1023) / 1024;
        block_sums<<<G, 256>>>((int*)pDegL, (int*)pBsums, NL);
        scan_bsums<<<1, 512>>>((int*)pBsums, G);
        scan_chunks<<<G, 256>>>((int*)pDegL, (int*)pBsums, (int*)pOffL, NL);
    }
    fill_csr<<<EB, 256>>>(lit_idx, clause_idx, (int*)pOffL, (int*)pCurL, (int*)pCsrL, n_edges);

    init_Lh<<<(NL * 32 + 255) / 256, 256>>>(L_init);

    const int CB = (NC + 7) / 8;     // gather_clause blocks (8 warps each)
    const int LB = (NL + 7) / 8;

    for (int hop = 0; hop < 4; hop++) {
        // ---- clause update ----
        gather_clause<<<CB, 256>>>();
        sgemm<true, 256, 256><<<dim3(2, (NC + 127) / 128), 256>>>(Cmsg, Cu_W1, Cu_b1, Chid, NC);
        sgemm<false, 256, 128><<<dim3(1, (NC + 127) / 128), 256>>>(Chid, Cu_W2, Cu_b2, C, NC);
        cudaMemsetAsync(pStats, 0, 512 * sizeof(float));
        col_stats<<<1024, 128>>>(NC);
        finalize_stats<<<1, 128>>>(NC);
        normalize_C<<<(NC * 32 + 255) / 256, 256>>>();
        // ---- literal update ----
        gather_lit<<<LB, 256>>>();
        sgemm<true, 128, 128><<<dim3(1, (NL + 127) / 128), 256>>>(Lmsg, Lu_W1, Lu_b1, Lhid, NL);
        sgemm<false, 128, 128><<<dim3(1, (NL + 127) / 128), 256>>>(Lhid, Lu_W2, Lu_b2, Lmsg, NL);
        add_ln<<<(NL + 7) / 8, 256>>>(Lmsg, ln_g, ln_b, NL);
    }

    // ---- heads ----
    concat_V<<<(HALFL * 64 + 255) / 256, 256>>>();   // V lives in g_Cmsg
    sgemm<true, 256, 256><<<dim3(2, (HALFL + 127) / 128), 256>>>(Cmsg, Vd_W1, Vd_b1, Chid, HALFL);
    rowdot<256><<<(HALFL + 7) / 8, 256>>>(Chid, Vd_W2, Vd_b2, out, HALFL);
    sgemm<true, 256, 256><<<dim3(2, (HALFL + 127) / 128), 256>>>(Cmsg, Vc_W1, Vc_b1, Chid, HALFL);
    rowdot<256><<<(HALFL + 7) / 8, 256>>>(Chid, Vc_W2, Vc_b2, out + HALFL, HALFL);
    sgemm<true, 128, 128><<<dim3(1, (NC + 127) / 128), 256>>>(C, Cs_W1, Cs_b1, Shid, NC);
    rowdot<128><<<(NC + 7) / 8, 256>>>(Shid, Cs_W2, Cs_b2, out + 2 * HALFL, NC);
}

// round 5
// speedup vs baseline: 2.0842x; 1.2514x over previous
#include <cuda_runtime.h>
#include <cstdint>
#include <cstddef>

// Problem constants (fixed by setup_inputs)
#define NC 300000      // n_clauses
#define NL 200000      // n_lits
#define HALFL 100000   // n_lits / 2
#define NE_MAX 1000000 // n_edges

// ---------------- static scratch (no allocation allowed) ----------------
__device__ float g_Lh  [(size_t)NL * 128];   // literal embeddings
__device__ float g_Lnew[(size_t)NL * 128];   // Lu2 output
__device__ float g_Lmsg[(size_t)NL * 128];   // L message
__device__ float g_Lhid[(size_t)NL * 128];   // L MLP hidden
__device__ float g_Cmsg[(size_t)NC * 256];   // clause message / reused as V
__device__ float g_Chid[(size_t)NC * 256];   // clause MLP hidden / head hidden
__device__ float g_C   [(size_t)NC * 128];   // clause embeddings (normalized)
__device__ float g_stats[512];               // colsum | colsumsq | mean | rstd

// transposed weights: Bt[n*K + k] = W[k*N + n]
__device__ float g_CuW1t[256 * 256];
__device__ float g_CuW2t[128 * 256];
__device__ float g_LuW1t[128 * 128];
__device__ float g_LuW2t[128 * 128];
__device__ float g_VdW1t[256 * 256];
__device__ float g_VcW1t[256 * 256];
__device__ float g_CsW1t[128 * 128];

// CSR scratch
__device__ int g_deg_c[NC];
__device__ int g_off_c[NC];
__device__ int g_cur_c[NC];
__device__ int g_csr_c[NE_MAX];
__device__ int g_deg_l[NL];
__device__ int g_off_l[NL];
__device__ int g_cur_l[NL];
__device__ int g_csr_l[NE_MAX];
__device__ int g_bsums[1024];

// ---------------- helpers ----------------
__device__ __forceinline__ float warp_sum(float v) {
    #pragma unroll
    for (int o = 16; o > 0; o >>= 1) v += __shfl_xor_sync(0xFFFFFFFFu, v, o);
    return v;
}
__device__ __forceinline__ int warp_sum_i(int v) {
    #pragma unroll
    for (int o = 16; o > 0; o >>= 1) v += __shfl_xor_sync(0xFFFFFFFFu, v, o);
    return v;
}
__device__ __forceinline__ uint32_t f2tf32(float x) {
    uint32_t r;
    asm("cvt.rna.tf32.f32 %0, %1;" : "=r"(r) : "f"(x));
    return r;
}
__device__ __forceinline__ void mma_tf32(float* c, const uint32_t* a, const uint32_t* b) {
    asm volatile("mma.sync.aligned.m16n8k8.row.col.f32.tf32.tf32.f32 "
                 "{%0,%1,%2,%3}, {%4,%5,%6,%7}, {%8,%9}, {%0,%1,%2,%3};"
                 : "+f"(c[0]), "+f"(c[1]), "+f"(c[2]), "+f"(c[3])
                 : "r"(a[0]), "r"(a[1]), "r"(a[2]), "r"(a[3]), "r"(b[0]), "r"(b[1]));
}

// ---------------- CSR build ----------------
__global__ void histogram(const int* __restrict__ key, int* __restrict__ deg, int ne) {
    int e = blockIdx.x * blockDim.x + threadIdx.x;
    if (e < ne) atomicAdd(&deg[key[e]], 1);
}
__global__ void block_sums(const int* __restrict__ deg, int* __restrict__ bsums, int n) {
    __shared__ int total;
    int b = blockIdx.x, t = threadIdx.x;
    if (t == 0) total = 0;
    __syncthreads();
    int base = b * 1024;
    int s = 0;
    for (int i = t; i < 1024; i += 256) {
        int idx = base + i;
        if (idx < n) s += deg[idx];
    }
    s = warp_sum_i(s);
    if ((t & 31) == 0) atomicAdd(&total, s);
    __syncthreads();
    if (t == 0) bsums[b] = total;
}
__global__ void scan_bsums(int* bsums, int G) {
    __shared__ int sh[512];
    int t = threadIdx.x;
    int v = (t < G) ? bsums[t] : 0;
    sh[t] = v;
    __syncthreads();
    #pragma unroll
    for (int o = 1; o < 512; o <<= 1) {
        int u = (t >= o) ? sh[t - o] : 0;
        __syncthreads();
        sh[t] += u;
        __syncthreads();
    }
    if (t < G) bsums[t] = sh[t] - v;
}
__global__ void scan_chunks(const int* __restrict__ deg, const int* __restrict__ bsums,
                            int* __restrict__ off, int n) {
    __shared__ int th[256];
    int b = blockIdx.x, t = threadIdx.x;
    int base = b * 1024 + t * 4;
    int v0 = 0, v1 = 0, v2 = 0, v3 = 0;
    if (base + 0 < n) v0 = deg[base + 0];
    if (base + 1 < n) v1 = deg[base + 1];
    if (base + 2 < n) v2 = deg[base + 2];
    if (base + 3 < n) v3 = deg[base + 3];
    int s = v0 + v1 + v2 + v3;
    th[t] = s;
    __syncthreads();
    #pragma unroll
    for (int o = 1; o < 256; o <<= 1) {
        int u = (t >= o) ? th[t - o] : 0;
        __syncthreads();
        th[t] += u;
        __syncthreads();
    }
    int pre = bsums[b] + th[t] - s;
    if (base + 0 < n) off[base + 0] = pre;
    pre += v0;
    if (base + 1 < n) off[base + 1] = pre;
    pre += v1;
    if (base + 2 < n) off[base + 2] = pre;
    pre += v2;
    if (base + 3 < n) off[base + 3] = pre;
}
__global__ void fill_csr(const int* __restrict__ key, const int* __restrict__ val,
                         const int* __restrict__ off, int* __restrict__ cur,
                         int* __restrict__ out, int ne) {
    int e = blockIdx.x * blockDim.x + threadIdx.x;
    if (e >= ne) return;
    int k = key[e];
    int p = off[k] + atomicAdd(&cur[k], 1);
    out[p] = val[e];
}

// ---------------- init / weight transpose ----------------
__global__ void init_Lh(const float* __restrict__ L_init) {
    int idx = blockIdx.x * blockDim.x + threadIdx.x;
    int total = NL * 32;
    if (idx >= total) return;
    int c4 = (idx & 31) * 4;
    float4 v = *(const float4*)&L_init[c4];
    *(float4*)&g_Lh[(size_t)idx * 4] = v;
}
__global__ void conv_wT(const float* __restrict__ W, float* __restrict__ Bt, int K, int N) {
    int idx = blockIdx.x * blockDim.x + threadIdx.x;
    if (idx >= K * N) return;
    int k = idx / N, n = idx % N;
    Bt[(size_t)n * K + k] = W[idx];
}

// ---------------- gathers (CSR, no atomics) ----------------
__global__ void gather_clause() {
    int c    = (blockIdx.x * blockDim.x + threadIdx.x) >> 5;
    int lane = threadIdx.x & 31;
    if (c >= NC) return;
    int o = g_off_c[c];
    int d = g_deg_c[c];
    float4 a = make_float4(0.f, 0.f, 0.f, 0.f);
    float4 b = make_float4(0.f, 0.f, 0.f, 0.f);
    for (int i = 0; i < d; i++) {
        int lit  = g_csr_c[o + i];
        int flip = (lit >= HALFL) ? (lit - HALFL) : (lit + HALFL);
        float4 x = *(const float4*)&g_Lh[(size_t)lit  * 128 + lane * 4];
        float4 y = *(const float4*)&g_Lh[(size_t)flip * 128 + lane * 4];
        a.x += x.x; a.y += x.y; a.z += x.z; a.w += x.w;
        b.x += y.x; b.y += y.y; b.z += y.z; b.w += y.w;
    }
    float* p = &g_Cmsg[(size_t)c * 256 + lane * 4];
    *(float4*)p         = a;
    *(float4*)(p + 128) = b;
}
__global__ void gather_lit() {
    int l    = (blockIdx.x * blockDim.x + threadIdx.x) >> 5;
    int lane = threadIdx.x & 31;
    if (l >= NL) return;
    int o = g_off_l[l];
    int d = g_deg_l[l];
    float4 a = make_float4(0.f, 0.f, 0.f, 0.f);
    for (int i = 0; i < d; i++) {
        int cl = g_csr_l[o + i];
        float4 x = *(const float4*)&g_C[(size_t)cl * 128 + lane * 4];
        a.x += x.x; a.y += x.y; a.z += x.z; a.w += x.w;
    }
    *(float4*)&g_Lmsg[(size_t)l * 128 + lane * 4] = a;
}

// ---------------- 3xTF32 HMMA GEMM ----------------
// Out[M,Nld] = (relu?)(A @ W + bias). A fp32 [M,K]; W transposed fp32 Bt [Nld,K].
// In-SMEM hi/lo tf32 split: D = Ah@Bh + Ah@Bl + Al@Bh via mma m16n8k8 tf32.
// CTA tile 128x128, 8 warps of 64x32, BK=32 chunks, SPAD=36 padded rows.
#define SPAD 36
#define TILE_F (128 * SPAD)
#define GEMM_SMEM_BYTES (4 * TILE_F * 4)

template<int K, bool RELU>
__global__ __launch_bounds__(256)
void tf32_gemm(const float* __restrict__ A, const float* __restrict__ Bt,
               const float* __restrict__ bias, float* __restrict__ Out,
               int M, int Nld) {
    extern __shared__ float sm[];
    float* sAh = sm;
    float* sAl = sm + TILE_F;
    float* sBh = sm + 2 * TILE_F;
    float* sBl = sm + 3 * TILE_F;

    const int tid  = threadIdx.x;
    const int wid  = tid >> 5;
    const int lane = tid & 31;
    const int brow = blockIdx.y * 128;
    const int bcol = blockIdx.x * 128;
    const int wr = wid & 1;     // 0/1 -> rows wr*64
    const int wc = wid >> 1;    // 0..3 -> cols wc*32
    const int grp = lane >> 2;  // 0..7
    const int qc  = lane & 3;   // 0..3

    float acc[4][4][4] = {};

    const float* BtP = Bt + (size_t)bcol * K;

    #pragma unroll 1
    for (int k0 = 0; k0 < K; k0 += 32) {
        // fill SMEM: per iter, each thread handles 8 floats of A and 8 of B
        #pragma unroll
        for (int i = 0; i < 2; i++) {
            int v  = tid + i * 256;            // 0..511
            int r  = v >> 2;                   // 0..127
            int ce = (v & 3) * 8;              // 0,8,16,24
            int so = r * SPAD + ce;
            bool av = (brow + r) < M;
            float4 z = make_float4(0.f, 0.f, 0.f, 0.f);
            float4 x0 = av ? *(const float4*)(A + (size_t)(brow + r) * K + k0 + ce)     : z;
            float4 x1 = av ? *(const float4*)(A + (size_t)(brow + r) * K + k0 + ce + 4) : z;
            float xa[8] = {x0.x, x0.y, x0.z, x0.w, x1.x, x1.y, x1.z, x1.w};
            #pragma unroll
            for (int j = 0; j < 8; j++) {
                uint32_t h = f2tf32(xa[j]);
                float hf = __uint_as_float(h);
                sAh[so + j] = hf;
                sAl[so + j] = __uint_as_float(f2tf32(xa[j] - hf));
            }
            float4 w0 = *(const float4*)(BtP + (size_t)r * K + k0 + ce);
            float4 w1 = *(const float4*)(BtP + (size_t)r * K + k0 + ce + 4);
            float wa[8] = {w0.x, w0.y, w0.z, w0.w, w1.x, w1.y, w1.z, w1.w};
            #pragma unroll
            for (int j = 0; j < 8; j++) {
                uint32_t h = f2tf32(wa[j]);
                float hf = __uint_as_float(h);
                sBh[so + j] = hf;
                sBl[so + j] = __uint_as_float(f2tf32(wa[j] - hf));
            }
        }
        __syncthreads();

        #pragma unroll
        for (int ks = 0; ks < 4; ks++) {
            int kk = ks * 8;
            // B fragments for the 4 n-tiles (hi & lo)
            uint32_t bh[4][2], bl[4][2];
            #pragma unroll
            for (int nt = 0; nt < 4; nt++) {
                int n0 = wc * 32 + nt * 8 + grp;
                int o0 = n0 * SPAD + kk + qc;
                bh[nt][0] = __float_as_uint(sBh[o0]);
                bh[nt][1] = __float_as_uint(sBh[o0 + 4]);
                bl[nt][0] = __float_as_uint(sBl[o0]);
                bl[nt][1] = __float_as_uint(sBl[o0 + 4]);
            }
            #pragma unroll
            for (int mt = 0; mt < 4; mt++) {
                int m0 = wr * 64 + mt * 16 + grp;
                int o0 = m0 * SPAD + kk + qc;
                int o1 = o0 + 8 * SPAD;
                uint32_t ah[4], al[4];
                ah[0] = __float_as_uint(sAh[o0]);
                ah[1] = __float_as_uint(sAh[o1]);
                ah[2] = __float_as_uint(sAh[o0 + 4]);
                ah[3] = __float_as_uint(sAh[o1 + 4]);
                al[0] = __float_as_uint(sAl[o0]);
                al[1] = __float_as_uint(sAl[o1]);
                al[2] = __float_as_uint(sAl[o0 + 4]);
                al[3] = __float_as_uint(sAl[o1 + 4]);
                #pragma unroll
                for (int nt = 0; nt < 4; nt++) {
                    mma_tf32(acc[mt][nt], ah, bh[nt]);
                    mma_tf32(acc[mt][nt], ah, bl[nt]);
                    mma_tf32(acc[mt][nt], al, bh[nt]);
                }
            }
        }
        __syncthreads();
    }

    // epilogue
    const int q     = lane >> 2;        // row-within-8
    const int tcol2 = (lane & 3) * 2;
    #pragma unroll
    for (int nt = 0; nt < 4; nt++) {
        int col = bcol + wc * 32 + nt * 8 + tcol2;
        float b0 = __ldg(&bias[col]), b1 = __ldg(&bias[col + 1]);
        #pragma unroll
        for (int mt = 0; mt < 4; mt++) {
            int rm0 = brow + wr * 64 + mt * 16 + q;
            int rm1 = rm0 + 8;
            float v0 = acc[mt][nt][0] + b0, v1 = acc[mt][nt][1] + b1;
            float v2 = acc[mt][nt][2] + b0, v3 = acc[mt][nt][3] + b1;
            if (RELU) {
                v0 = fmaxf(v0, 0.f); v1 = fmaxf(v1, 0.f);
                v2 = fmaxf(v2, 0.f); v3 = fmaxf(v3, 0.f);
            }
            if (rm0 < M) *(float2*)&Out[(size_t)rm0 * Nld + col] = make_float2(v0, v1);
            if (rm1 < M) *(float2*)&Out[(size_t)rm1 * Nld + col] = make_float2(v2, v3);
        }
    }
}

// ---------------- column stats over C [M,128] ----------------
__global__ void col_stats(int M) {
    int col = threadIdx.x;
    float s = 0.f, ss = 0.f;
    for (int r = blockIdx.x; r < M; r += gridDim.x) {
        float v = g_C[(size_t)r * 128 + col];
        s  += v;
        ss += v * v;
    }
    atomicAdd(&g_stats[col],       s);
    atomicAdd(&g_stats[128 + col], ss);
}
__global__ void finalize_stats(int M) {
    int col = threadIdx.x;
    float n    = (float)M;
    float sum  = g_stats[col];
    float sumq = g_stats[128 + col];
    float mean = sum / n;
    float var  = (sumq - n * mean * mean) / (n - 1.0f);
    var = fmaxf(var, 0.f);
    float rstd = 1.0f / (sqrtf(var) + 1e-10f);
    g_stats[256 + col] = mean;
    g_stats[384 + col] = rstd;
}
__global__ void normalize_C() {
    int idx = blockIdx.x * blockDim.x + threadIdx.x;
    int total = NC * 32;
    if (idx >= total) return;
    int c4 = (idx & 31) * 4;
    float4 v = *(const float4*)&g_C[(size_t)idx * 4];
    float4 m = *(const float4*)&g_stats[256 + c4];
    float4 r = *(const float4*)&g_stats[384 + c4];
    v.x = (v.x - m.x) * r.x; v.y = (v.y - m.y) * r.y;
    v.z = (v.z - m.z) * r.z; v.w = (v.w - m.w) * r.w;
    *(float4*)&g_C[(size_t)idx * 4] = v;
}

// ---------------- Lh = LayerNorm(Lnew + 0.1*Lh) * g + b ----------------
__global__ void add_ln(const float* __restrict__ Lnew,
                       const float* __restrict__ lng,
                       const float* __restrict__ lnb, int M) {
    int row  = (blockIdx.x * blockDim.x + threadIdx.x) >> 5;
    int lane = threadIdx.x & 31;
    if (row >= M) return;
    size_t base = (size_t)row * 128 + lane * 4;
    float4 xn = *(const float4*)&Lnew[base];
    float4 xo = *(const float4*)&g_Lh[base];
    float4 x;
    x.x = fmaf(0.1f, xo.x, xn.x); x.y = fmaf(0.1f, xo.y, xn.y);
    x.z = fmaf(0.1f, xo.z, xn.z); x.w = fmaf(0.1f, xo.w, xn.w);
    float mean = warp_sum(x.x + x.y + x.z + x.w) * (1.0f / 128.0f);
    float dx = x.x - mean, dy = x.y - mean, dz = x.z - mean, dw = x.w - mean;
    float var = warp_sum(dx * dx + dy * dy + dz * dz + dw * dw) * (1.0f / 128.0f);
    float rstd = rsqrtf(var + 1e-5f);
    float4 gg = *(const float4*)&lng[lane * 4];
    float4 bb = *(const float4*)&lnb[lane * 4];
    float4 y;
    y.x = fmaf(dx * rstd, gg.x, bb.x);
    y.y = fmaf(dy * rstd, gg.y, bb.y);
    y.z = fmaf(dz * rstd, gg.z, bb.z);
    y.w = fmaf(dw * rstd, gg.w, bb.w);
    *(float4*)&g_Lh[base] = y;
}

// ---------------- V = [Lh[:half], Lh[half:]] -> g_Cmsg ----------------
__global__ void concat_V() {
    int idx = blockIdx.x * blockDim.x + threadIdx.x;
    int total = HALFL * 64;
    if (idx >= total) return;
    int v  = idx >> 6;
    int c4 = idx & 63;
    float4 x;
    if (c4 < 32) x = *(const float4*)&g_Lh[(size_t)v * 128 + c4 * 4];
    else         x = *(const float4*)&g_Lh[(size_t)(v + HALFL) * 128 + (c4 - 32) * 4];
    *(float4*)&g_Cmsg[(size_t)v * 256 + c4 * 4] = x;
}

// ---------------- out[m] = dot(H[m,:K], w) + b ----------------
template<int K>
__global__ void rowdot(const float* __restrict__ H, const float* __restrict__ w,
                       const float* __restrict__ b, float* __restrict__ out, int M) {
    int row  = (blockIdx.x * blockDim.x + threadIdx.x) >> 5;
    int lane = threadIdx.x & 31;
    if (row >= M) return;
    float acc = 0.f;
    #pragma unroll
    for (int k0 = 0; k0 < K; k0 += 128) {
        float4 h  = *(const float4*)&H[(size_t)row * K + k0 + lane * 4];
        float4 ww = *(const float4*)&w[k0 + lane * 4];
        acc = fmaf(h.x, ww.x, acc);
        acc = fmaf(h.y, ww.y, acc);
        acc = fmaf(h.z, ww.z, acc);
        acc = fmaf(h.w, ww.w, acc);
    }
    acc = warp_sum(acc);
    if (lane == 0) out[row] = acc + b[0];
}

// ---------------- host orchestration ----------------
static void* sym(const void* s) { void* p; cudaGetSymbolAddress(&p, s); return p; }

extern "C" void kernel_launch(void* const* d_in, const int* in_sizes, int n_in,
                              void* d_out, int out_size) {
    const float* L_init = (const float*)d_in[0];
    const float* ln_g   = (const float*)d_in[1];
    const float* ln_b   = (const float*)d_in[2];
    const float* Cu_W1  = (const float*)d_in[3];
    const float* Cu_b1  = (const float*)d_in[4];
    const float* Cu_W2  = (const float*)d_in[5];
    const float* Cu_b2  = (const float*)d_in[6];
    const float* Lu_W1  = (const float*)d_in[7];
    const float* Lu_b1  = (const float*)d_in[8];
    const float* Lu_W2  = (const float*)d_in[9];
    const float* Lu_b2  = (const float*)d_in[10];
    const float* Vd_W1  = (const float*)d_in[11];
    const float* Vd_b1  = (const float*)d_in[12];
    const float* Vd_W2  = (const float*)d_in[13];
    const float* Vd_b2  = (const float*)d_in[14];
    const float* Vc_W1  = (const float*)d_in[15];
    const float* Vc_b1  = (const float*)d_in[16];
    const float* Vc_W2  = (const float*)d_in[17];
    const float* Vc_b2  = (const float*)d_in[18];
    const float* Cs_W1  = (const float*)d_in[19];
    const float* Cs_b1  = (const float*)d_in[20];
    const float* Cs_W2  = (const float*)d_in[21];
    const float* Cs_b2  = (const float*)d_in[22];
    const int* clause_idx = (const int*)d_in[23];
    const int* lit_idx    = (const int*)d_in[24];
    int n_edges = in_sizes[23];
    float* out = (float*)d_out;

    float* C    = (float*)sym(g_C);
    float* Lnew = (float*)sym(g_Lnew);
    float* Lmsg = (float*)sym(g_Lmsg);
    float* Lhid = (float*)sym(g_Lhid);
    float* Cmsg = (float*)sym(g_Cmsg);
    float* Chid = (float*)sym(g_Chid);
    float* CuW1t = (float*)sym(g_CuW1t);
    float* CuW2t = (float*)sym(g_CuW2t);
    float* LuW1t = (float*)sym(g_LuW1t);
    float* LuW2t = (float*)sym(g_LuW2t);
    float* VdW1t = (float*)sym(g_VdW1t);
    float* VcW1t = (float*)sym(g_VcW1t);
    float* CsW1t = (float*)sym(g_CsW1t);
    void* pStats = sym(g_stats);
    int* DegC = (int*)sym(g_deg_c); int* CurC = (int*)sym(g_cur_c);
    int* OffC = (int*)sym(g_off_c); int* CsrC = (int*)sym(g_csr_c);
    int* DegL = (int*)sym(g_deg_l); int* CurL = (int*)sym(g_cur_l);
    int* OffL = (int*)sym(g_off_l); int* CsrL = (int*)sym(g_csr_l);
    int* Bsums = (int*)sym(g_bsums);

    cudaFuncSetAttribute(tf32_gemm<256, true >, cudaFuncAttributeMaxDynamicSharedMemorySize, GEMM_SMEM_BYTES);
    cudaFuncSetAttribute(tf32_gemm<256, false>, cudaFuncAttributeMaxDynamicSharedMemorySize, GEMM_SMEM_BYTES);
    cudaFuncSetAttribute(tf32_gemm<128, true >, cudaFuncAttributeMaxDynamicSharedMemorySize, GEMM_SMEM_BYTES);
    cudaFuncSetAttribute(tf32_gemm<128, false>, cudaFuncAttributeMaxDynamicSharedMemorySize, GEMM_SMEM_BYTES);

    const int EB = (n_edges + 255) / 256;

    // ---- build CSR ----
    cudaMemsetAsync(DegC, 0, NC * sizeof(int));
    cudaMemsetAsync(CurC, 0, NC * sizeof(int));
    histogram<<<EB, 256>>>(clause_idx, DegC, n_edges);
    {
        int G = (NC + 1023) / 1024;
        block_sums<<<G, 256>>>(DegC, Bsums, NC);
        scan_bsums<<<1, 512>>>(Bsums, G);
        scan_chunks<<<G, 256>>>(DegC, Bsums, OffC, NC);
    }
    fill_csr<<<EB, 256>>>(clause_idx, lit_idx, OffC, CurC, CsrC, n_edges);

    cudaMemsetAsync(DegL, 0, NL * sizeof(int));
    cudaMemsetAsync(CurL, 0, NL * sizeof(int));
    histogram<<<EB, 256>>>(lit_idx, DegL, n_edges);
    {
        int G = (NL + 1023) / 1024;
        block_sums<<<G, 256>>>(DegL, Bsums, NL);
        scan_bsums<<<1, 512>>>(Bsums, G);
        scan_chunks<<<G, 256>>>(DegL, Bsums, OffL, NL);
    }
    fill_csr<<<EB, 256>>>(lit_idx, clause_idx, OffL, CurL, CsrL, n_edges);

    // ---- weights: transpose (once per launch) ----
    conv_wT<<<(256 * 256 + 255) / 256, 256>>>(Cu_W1, CuW1t, 256, 256);
    conv_wT<<<(256 * 128 + 255) / 256, 256>>>(Cu_W2, CuW2t, 256, 128);
    conv_wT<<<(128 * 128 + 255) / 256, 256>>>(Lu_W1, LuW1t, 128, 128);
    conv_wT<<<(128 * 128 + 255) / 256, 256>>>(Lu_W2, LuW2t, 128, 128);
    conv_wT<<<(256 * 256 + 255) / 256, 256>>>(Vd_W1, VdW1t, 256, 256);
    conv_wT<<<(256 * 256 + 255) / 256, 256>>>(Vc_W1, VcW1t, 256, 256);
    conv_wT<<<(128 * 128 + 255) / 256, 256>>>(Cs_W1, CsW1t, 128, 128);

    init_Lh<<<(NL * 32 + 255) / 256, 256>>>(L_init);

    const int GC = (NC + 127) / 128;      // 2344
    const int GL = (NL + 127) / 128;      // 1563
    const int GV = (HALFL + 127) / 128;   // 782

    for (int hop = 0; hop < 4; hop++) {
        gather_clause<<<(NC + 7) / 8, 256>>>();
        tf32_gemm<256, true ><<<dim3(2, GC), 256, GEMM_SMEM_BYTES>>>(Cmsg, CuW1t, Cu_b1, Chid, NC, 256);
        tf32_gemm<256, false><<<dim3(1, GC), 256, GEMM_SMEM_BYTES>>>(Chid, CuW2t, Cu_b2, C, NC, 128);
        cudaMemsetAsync(pStats, 0, 512 * sizeof(float));
        col_stats<<<1024, 128>>>(NC);
        finalize_stats<<<1, 128>>>(NC);
        normalize_C<<<(NC * 32 + 255) / 256, 256>>>();

        gather_lit<<<(NL + 7) / 8, 256>>>();
        tf32_gemm<128, true ><<<dim3(1, GL), 256, GEMM_SMEM_BYTES>>>(Lmsg, LuW1t, Lu_b1, Lhid, NL, 128);
        tf32_gemm<128, false><<<dim3(1, GL), 256, GEMM_SMEM_BYTES>>>(Lhid, LuW2t, Lu_b2, Lnew, NL, 128);
        add_ln<<<(NL + 7) / 8, 256>>>(Lnew, ln_g, ln_b, NL);
    }

    // ---- heads ----
    concat_V<<<(HALFL * 64 + 255) / 256, 256>>>();   // V lives in g_Cmsg
    tf32_gemm<256, true><<<dim3(2, GV), 256, GEMM_SMEM_BYTES>>>(Cmsg, VdW1t, Vd_b1, Chid, HALFL, 256);
    rowdot<256><<<(HALFL + 7) / 8, 256>>>(Chid, Vd_W2, Vd_b2, out, HALFL);
    tf32_gemm<256, true><<<dim3(2, GV), 256, GEMM_SMEM_BYTES>>>(Cmsg, VcW1t, Vc_b1, Chid, HALFL, 256);
    rowdot<256><<<(HALFL + 7) / 8, 256>>>(Chid, Vc_W2, Vc_b2, out + HALFL, HALFL);
    tf32_gemm<128, true><<<dim3(1, GC), 256, GEMM_SMEM_BYTES>>>(C, CsW1t, Cs_b1, Chid, NC, 128);
    rowdot<128><<<(NC + 7) / 8, 256>>>(Chid, Cs_W2, Cs_b2, out + 2 * HALFL, NC);
}